// round 1
// baseline (speedup 1.0000x reference)
#include <cuda_runtime.h>
#include <math.h>

#define D_MODEL   3072
#define NUM_E     8
#define N_TOKENS  16384      // 4 * 4096
#define TPW       4          // tokens per warp
#define WARPS_PB  8
#define THREADS   (WARPS_PB * 32)
#define CHUNKS    (D_MODEL / 128)   // 24: 32 lanes * float4 per chunk
#define SMEM_W_BYTES (NUM_E * D_MODEL * sizeof(float))   // 96 KB

__global__ void __launch_bounds__(THREADS, 2)
gating_kernel(const float* __restrict__ x,
              const float* __restrict__ W,
              const float* __restrict__ b,
              float* __restrict__ out,
              int idx_off)   // element offset of the index half of the output
{
    extern __shared__ float sW[];   // [NUM_E][D_MODEL]

    // Cooperative load of W into shared memory (float4, coalesced).
    {
        const float4* Wv = reinterpret_cast<const float4*>(W);
        float4* sWv = reinterpret_cast<float4*>(sW);
        #pragma unroll 4
        for (int i = threadIdx.x; i < NUM_E * D_MODEL / 4; i += THREADS)
            sWv[i] = Wv[i];
    }
    __syncthreads();

    const int warp = threadIdx.x >> 5;
    const int lane = threadIdx.x & 31;
    const int tok0 = (blockIdx.x * WARPS_PB + warp) * TPW;

    const float* xp = x + (size_t)tok0 * D_MODEL;

    float acc[TPW][NUM_E];
    #pragma unroll
    for (int t = 0; t < TPW; ++t)
        #pragma unroll
        for (int e = 0; e < NUM_E; ++e)
            acc[t][e] = 0.0f;

    // Main loop: each lane owns float4 chunks strided by 32 across D.
    #pragma unroll 2
    for (int c = 0; c < CHUNKS; ++c) {
        const int d = (c * 32 + lane) * 4;

        float4 xv[TPW];
        #pragma unroll
        for (int t = 0; t < TPW; ++t)
            xv[t] = *reinterpret_cast<const float4*>(xp + (size_t)t * D_MODEL + d);

        #pragma unroll
        for (int e = 0; e < NUM_E; ++e) {
            const float4 wv = *reinterpret_cast<const float4*>(sW + e * D_MODEL + d);
            #pragma unroll
            for (int t = 0; t < TPW; ++t) {
                acc[t][e] = fmaf(xv[t].x, wv.x, acc[t][e]);
                acc[t][e] = fmaf(xv[t].y, wv.y, acc[t][e]);
                acc[t][e] = fmaf(xv[t].z, wv.z, acc[t][e]);
                acc[t][e] = fmaf(xv[t].w, wv.w, acc[t][e]);
            }
        }
    }

    // Warp butterfly reduction: every lane ends with the full dot products.
    #pragma unroll
    for (int off = 16; off > 0; off >>= 1) {
        #pragma unroll
        for (int t = 0; t < TPW; ++t)
            #pragma unroll
            for (int e = 0; e < NUM_E; ++e)
                acc[t][e] += __shfl_xor_sync(0xFFFFFFFFu, acc[t][e], off);
    }

    // Lanes 0..TPW-1: one token each. Softmax over 8, top-2, renorm softmax.
    if (lane < TPW) {
        const int tok = tok0 + lane;

        float logit[NUM_E];
        #pragma unroll
        for (int e = 0; e < NUM_E; ++e)
            logit[e] = acc[lane][e] + __ldg(&b[e]);

        float m = logit[0];
        #pragma unroll
        for (int e = 1; e < NUM_E; ++e) m = fmaxf(m, logit[e]);

        float ex[NUM_E];
        float Z = 0.0f;
        #pragma unroll
        for (int e = 0; e < NUM_E; ++e) { ex[e] = __expf(logit[e] - m); Z += ex[e]; }
        const float invZ = 1.0f / Z;

        float sc[NUM_E];
        #pragma unroll
        for (int e = 0; e < NUM_E; ++e) sc[e] = ex[e] * invZ;

        // top-1 (ties -> lowest index, matching jax.lax.top_k)
        int i1 = 0;
        #pragma unroll
        for (int e = 1; e < NUM_E; ++e) if (sc[e] > sc[i1]) i1 = e;
        // top-2
        int i2 = (i1 == 0) ? 1 : 0;
        #pragma unroll
        for (int e = 0; e < NUM_E; ++e)
            if (e != i1 && (sc[e] > sc[i2] || (sc[e] == sc[i2] && e < i2 && i2 != ((i1==0)?1:0) ))) {
                if (sc[e] > sc[i2]) i2 = e;
            }
        // (strict > scan keeps earliest index on exact ties)

        const float v1 = sc[i1];
        const float v2 = sc[i2];
        // renormalizing softmax over (v1, v2), v1 >= v2
        const float e2 = __expf(v2 - v1);
        const float r1 = 1.0f / (1.0f + e2);
        const float r2 = 1.0f - r1;

        out[(size_t)tok * 2 + 0] = r1;
        out[(size_t)tok * 2 + 1] = r2;
        out[(size_t)idx_off + (size_t)tok * 2 + 0] = (float)i1;
        out[(size_t)idx_off + (size_t)tok * 2 + 1] = (float)i2;
    }
}

extern "C" void kernel_launch(void* const* d_in, const int* in_sizes, int n_in,
                              void* d_out, int out_size)
{
    const float* x = (const float*)d_in[0];
    const float* W = (const float*)d_in[1];
    const float* b = (const float*)d_in[2];
    float* out = (float*)d_out;

    // Output layout: first half = top-k values, second half = indices (as float).
    const int idx_off = out_size / 2;

    static bool attr_set = false;
    if (!attr_set) {
        cudaFuncSetAttribute(gating_kernel,
                             cudaFuncAttributeMaxDynamicSharedMemorySize,
                             (int)SMEM_W_BYTES);
        attr_set = true;
    }

    const int tokens_per_block = WARPS_PB * TPW;     // 32
    const int grid = N_TOKENS / tokens_per_block;    // 512

    gating_kernel<<<grid, THREADS, SMEM_W_BYTES>>>(x, W, b, out, idx_off);
}

// round 2
// speedup vs baseline: 1.0062x; 1.0062x over previous
#include <cuda_runtime.h>
#include <math.h>

#define D_MODEL   3072
#define NUM_E     8
#define N_TOKENS  16384      // 4 * 4096
#define TPW       4          // tokens per warp
#define WARPS_PB  8
#define THREADS   (WARPS_PB * 32)
#define CHUNKS    (D_MODEL / 128)   // 24: 32 lanes * float4 per chunk
#define ROW_V     (D_MODEL / 4)     // 768 ulonglong2 (16B) elements per row
#define SMEM_W_BYTES (NUM_E * D_MODEL * sizeof(float))   // 96 KB

typedef unsigned long long u64;

// Packed dual-FMA: d = a*b + c on two fp32 lanes (sm_103a f32x2 pipe).
__device__ __forceinline__ u64 ffma2(u64 a, u64 b, u64 c) {
    u64 d;
    asm("fma.rn.f32x2 %0, %1, %2, %3;" : "=l"(d) : "l"(a), "l"(b), "l"(c));
    return d;
}

__device__ __forceinline__ float unpack_sum(u64 v) {
    float lo = __uint_as_float((unsigned)(v & 0xFFFFFFFFull));
    float hi = __uint_as_float((unsigned)(v >> 32));
    return lo + hi;
}

__global__ void __launch_bounds__(THREADS, 2)
gating_kernel(const float* __restrict__ x,
              const float* __restrict__ W,
              const float* __restrict__ b,
              float* __restrict__ out,
              int idx_off)
{
    extern __shared__ float sW[];   // [NUM_E][D_MODEL]

    // Cooperative load of W into shared memory (float4, coalesced).
    {
        const float4* Wv = reinterpret_cast<const float4*>(W);
        float4* sWv4 = reinterpret_cast<float4*>(sW);
        #pragma unroll 4
        for (int i = threadIdx.x; i < NUM_E * D_MODEL / 4; i += THREADS)
            sWv4[i] = Wv[i];
    }
    __syncthreads();

    const int warp = threadIdx.x >> 5;
    const int lane = threadIdx.x & 31;
    const int tok0 = (blockIdx.x * WARPS_PB + warp) * TPW;

    const ulonglong2* __restrict__ xrow =
        reinterpret_cast<const ulonglong2*>(x) + (size_t)tok0 * ROW_V;
    const ulonglong2* __restrict__ sWv =
        reinterpret_cast<const ulonglong2*>(sW);

    u64 acc[TPW][NUM_E];
    #pragma unroll
    for (int t = 0; t < TPW; ++t)
        #pragma unroll
        for (int e = 0; e < NUM_E; ++e)
            acc[t][e] = 0ull;

    ulonglong2 xa[TPW], xb[TPW];

    // prologue: chunk 0
    #pragma unroll
    for (int t = 0; t < TPW; ++t)
        xa[t] = xrow[t * ROW_V + lane];

    #pragma unroll 2
    for (int c = 0; c < CHUNKS; c += 2) {
        const int i0 = c * 32 + lane;
        const int i1 = i0 + 32;
        const int i2 = i0 + 64;

        // prefetch chunk c+1
        #pragma unroll
        for (int t = 0; t < TPW; ++t)
            xb[t] = xrow[t * ROW_V + i1];

        // compute chunk c
        #pragma unroll
        for (int e = 0; e < NUM_E; ++e) {
            const ulonglong2 wv = sWv[e * ROW_V + i0];
            #pragma unroll
            for (int t = 0; t < TPW; ++t) {
                acc[t][e] = ffma2(xa[t].x, wv.x, acc[t][e]);
                acc[t][e] = ffma2(xa[t].y, wv.y, acc[t][e]);
            }
        }

        // prefetch chunk c+2
        if (c + 2 < CHUNKS) {
            #pragma unroll
            for (int t = 0; t < TPW; ++t)
                xa[t] = xrow[t * ROW_V + i2];
        }

        // compute chunk c+1
        #pragma unroll
        for (int e = 0; e < NUM_E; ++e) {
            const ulonglong2 wv = sWv[e * ROW_V + i1];
            #pragma unroll
            for (int t = 0; t < TPW; ++t) {
                acc[t][e] = ffma2(xb[t].x, wv.x, acc[t][e]);
                acc[t][e] = ffma2(xb[t].y, wv.y, acc[t][e]);
            }
        }
    }

    // Collapse packed pairs, then warp butterfly reduction.
    float red[TPW][NUM_E];
    #pragma unroll
    for (int t = 0; t < TPW; ++t)
        #pragma unroll
        for (int e = 0; e < NUM_E; ++e)
            red[t][e] = unpack_sum(acc[t][e]);

    #pragma unroll
    for (int off = 16; off > 0; off >>= 1) {
        #pragma unroll
        for (int t = 0; t < TPW; ++t)
            #pragma unroll
            for (int e = 0; e < NUM_E; ++e)
                red[t][e] += __shfl_xor_sync(0xFFFFFFFFu, red[t][e], off);
    }

    // Lanes 0..TPW-1: one token each. Softmax over 8, top-2, renorm softmax.
    if (lane < TPW) {
        const int tok = tok0 + lane;

        float logit[NUM_E];
        #pragma unroll
        for (int e = 0; e < NUM_E; ++e)
            logit[e] = red[lane][e] + __ldg(&b[e]);

        float m = logit[0];
        #pragma unroll
        for (int e = 1; e < NUM_E; ++e) m = fmaxf(m, logit[e]);

        float ex[NUM_E];
        float Z = 0.0f;
        #pragma unroll
        for (int e = 0; e < NUM_E; ++e) { ex[e] = __expf(logit[e] - m); Z += ex[e]; }
        const float invZ = 1.0f / Z;

        float sc[NUM_E];
        #pragma unroll
        for (int e = 0; e < NUM_E; ++e) sc[e] = ex[e] * invZ;

        // top-1 (ties -> lowest index, matching jax.lax.top_k)
        int i1 = 0;
        #pragma unroll
        for (int e = 1; e < NUM_E; ++e) if (sc[e] > sc[i1]) i1 = e;
        // top-2: strict > scan keeps earliest index on exact ties
        int i2 = (i1 == 0) ? 1 : 0;
        #pragma unroll
        for (int e = 0; e < NUM_E; ++e)
            if (e != i1 && sc[e] > sc[i2]) i2 = e;

        const float v1 = sc[i1];
        const float v2 = sc[i2];
        // renormalizing softmax over (v1, v2), v1 >= v2
        const float e2 = __expf(v2 - v1);
        const float r1 = 1.0f / (1.0f + e2);
        const float r2 = 1.0f - r1;

        out[(size_t)tok * 2 + 0] = r1;
        out[(size_t)tok * 2 + 1] = r2;
        out[(size_t)idx_off + (size_t)tok * 2 + 0] = (float)i1;
        out[(size_t)idx_off + (size_t)tok * 2 + 1] = (float)i2;
    }
}

extern "C" void kernel_launch(void* const* d_in, const int* in_sizes, int n_in,
                              void* d_out, int out_size)
{
    const float* x = (const float*)d_in[0];
    const float* W = (const float*)d_in[1];
    const float* b = (const float*)d_in[2];
    float* out = (float*)d_out;

    const int idx_off = out_size / 2;

    static bool attr_set = false;
    if (!attr_set) {
        cudaFuncSetAttribute(gating_kernel,
                             cudaFuncAttributeMaxDynamicSharedMemorySize,
                             (int)SMEM_W_BYTES);
        attr_set = true;
    }

    const int tokens_per_block = WARPS_PB * TPW;     // 32
    const int grid = N_TOKENS / tokens_per_block;    // 512

    gating_kernel<<<grid, THREADS, SMEM_W_BYTES>>>(x, W, b, out, idx_off);
}

// round 3
// speedup vs baseline: 1.1031x; 1.0963x over previous
#include <cuda_runtime.h>
#include <math.h>

#define D_MODEL   3072
#define NUM_E     8
#define N_TOKENS  16384
#define TPW       4                     // tokens per warp
#define WARPS_PB  8
#define THREADS   (WARPS_PB * 32)
#define CHUNK_D   128                   // floats of D per pipeline stage
#define NCHUNK    (D_MODEL / CHUNK_D)   // 24
#define NSTAGE    6                     // per-warp ring depth
#define GROUPS    (N_TOKENS / (WARPS_PB * TPW))  // 512 token-groups of 32
#define GRID      148                   // persistent: 1 CTA per SM
#define ROW_V     (D_MODEL / 4)         // 768 16B elements per W row
#define RING_FLOATS_PER_WARP (NSTAGE * TPW * CHUNK_D)    // 3072
#define SMEM_BYTES ((NUM_E * D_MODEL + WARPS_PB * RING_FLOATS_PER_WARP) * 4)  // 192 KB

typedef unsigned long long u64;

__device__ __forceinline__ u64 ffma2(u64 a, u64 b, u64 c) {
    u64 d;
    asm("fma.rn.f32x2 %0, %1, %2, %3;" : "=l"(d) : "l"(a), "l"(b), "l"(c));
    return d;
}
__device__ __forceinline__ float unpack_sum(u64 v) {
    return __uint_as_float((unsigned)(v & 0xFFFFFFFFull)) +
           __uint_as_float((unsigned)(v >> 32));
}

__global__ void __launch_bounds__(THREADS, 1)
gating_kernel(const float* __restrict__ x,
              const float* __restrict__ W,
              const float* __restrict__ b,
              float* __restrict__ out,
              int idx_off)
{
    extern __shared__ float smem[];
    float* sW = smem;                                   // [8][3072]
    float* sX = smem + NUM_E * D_MODEL;                 // per-warp rings

    // Cooperative load of W into shared memory.
    {
        const float4* Wv = reinterpret_cast<const float4*>(W);
        float4* sWv4 = reinterpret_cast<float4*>(sW);
        #pragma unroll 4
        for (int i = threadIdx.x; i < NUM_E * D_MODEL / 4; i += THREADS)
            sWv4[i] = Wv[i];
    }
    __syncthreads();

    const int warp = threadIdx.x >> 5;
    const int lane = threadIdx.x & 31;

    float* ring = sX + warp * RING_FLOATS_PER_WARP;
    const unsigned ring_s =
        (unsigned)__cvta_generic_to_shared(ring) + lane * 16;
    const ulonglong2* __restrict__ ringv =
        reinterpret_cast<const ulonglong2*>(ring);
    const ulonglong2* __restrict__ sWv =
        reinterpret_cast<const ulonglong2*>(sW);

    // Persistent: this CTA handles groups g = bid, bid+GRID, ...
    const int bid = blockIdx.x;
    const int ng = (GROUPS - bid + GRID - 1) / GRID;   // 3 or 4
    const int T  = ng * NCHUNK;                        // total stages

    // stage t  ->  group j = t/24, chunk c = t%24, ring slot t%6
    #define ISSUE_STAGE(t_)                                                   \
        do {                                                                  \
            int _t = (t_);                                                    \
            int _j = _t / NCHUNK;                                             \
            int _c = _t - _j * NCHUNK;                                        \
            int _g = bid + _j * GRID;                                         \
            const float* _src = x + (size_t)(_g * (WARPS_PB * TPW) + warp * TPW) * D_MODEL \
                                  + _c * CHUNK_D + lane * 4;                  \
            unsigned _dst = ring_s + (_t % NSTAGE) * (TPW * CHUNK_D * 4);     \
            _Pragma("unroll")                                                 \
            for (int _tt = 0; _tt < TPW; ++_tt)                               \
                asm volatile("cp.async.cg.shared.global [%0], [%1], 16;"      \
                             :: "r"(_dst + _tt * (CHUNK_D * 4)),              \
                                "l"(_src + (size_t)_tt * D_MODEL));           \
        } while (0)

    u64 acc[TPW][NUM_E];
    #pragma unroll
    for (int t = 0; t < TPW; ++t)
        #pragma unroll
        for (int e = 0; e < NUM_E; ++e)
            acc[t][e] = 0ull;

    // Prologue: stages 0..NSTAGE-2 in flight.
    #pragma unroll
    for (int t = 0; t < NSTAGE - 1; ++t) {
        ISSUE_STAGE(t);
        asm volatile("cp.async.commit_group;" ::: "memory");
    }

    for (int t = 0; t < T; ++t) {
        // Stage t complete (<= NSTAGE-2 groups younger than it still pending).
        asm volatile("cp.async.wait_group 4;" ::: "memory");

        // Keep the pipe full; commit (possibly empty) every iteration so the
        // group FIFO count stays exact.
        if (t + NSTAGE - 1 < T) ISSUE_STAGE(t + NSTAGE - 1);
        asm volatile("cp.async.commit_group;" ::: "memory");

        const int j = t / NCHUNK;
        const int c = t - j * NCHUNK;
        const int slot = t % NSTAGE;

        const ulonglong2* xs = ringv + slot * (TPW * CHUNK_D / 4);
        ulonglong2 xv[TPW];
        #pragma unroll
        for (int tt = 0; tt < TPW; ++tt)
            xv[tt] = xs[tt * (CHUNK_D / 4) + lane];

        #pragma unroll
        for (int e = 0; e < NUM_E; ++e) {
            const ulonglong2 wv = sWv[e * ROW_V + c * (CHUNK_D / 4) + lane];
            #pragma unroll
            for (int tt = 0; tt < TPW; ++tt) {
                acc[tt][e] = ffma2(xv[tt].x, wv.x, acc[tt][e]);
                acc[tt][e] = ffma2(xv[tt].y, wv.y, acc[tt][e]);
            }
        }

        if (c == NCHUNK - 1) {
            // ---- epilogue for group g = bid + j*GRID ----
            const int g = bid + j * GRID;
            const int tok0 = g * (WARPS_PB * TPW) + warp * TPW;

            float red[TPW][NUM_E];
            #pragma unroll
            for (int tt = 0; tt < TPW; ++tt)
                #pragma unroll
                for (int e = 0; e < NUM_E; ++e) {
                    red[tt][e] = unpack_sum(acc[tt][e]);
                    acc[tt][e] = 0ull;
                }

            #pragma unroll
            for (int off = 16; off > 0; off >>= 1)
                #pragma unroll
                for (int tt = 0; tt < TPW; ++tt)
                    #pragma unroll
                    for (int e = 0; e < NUM_E; ++e)
                        red[tt][e] += __shfl_xor_sync(0xFFFFFFFFu, red[tt][e], off);

            if (lane < TPW) {
                const int tok = tok0 + lane;

                float logit[NUM_E];
                #pragma unroll
                for (int e = 0; e < NUM_E; ++e)
                    logit[e] = red[lane][e] + __ldg(&b[e]);

                float m = logit[0];
                #pragma unroll
                for (int e = 1; e < NUM_E; ++e) m = fmaxf(m, logit[e]);

                float ex[NUM_E], Z = 0.0f;
                #pragma unroll
                for (int e = 0; e < NUM_E; ++e) { ex[e] = __expf(logit[e] - m); Z += ex[e]; }
                const float invZ = 1.0f / Z;

                float sc[NUM_E];
                #pragma unroll
                for (int e = 0; e < NUM_E; ++e) sc[e] = ex[e] * invZ;

                int i1 = 0;
                #pragma unroll
                for (int e = 1; e < NUM_E; ++e) if (sc[e] > sc[i1]) i1 = e;
                int i2 = (i1 == 0) ? 1 : 0;
                #pragma unroll
                for (int e = 0; e < NUM_E; ++e)
                    if (e != i1 && sc[e] > sc[i2]) i2 = e;

                const float v1 = sc[i1];
                const float v2 = sc[i2];
                const float e2 = __expf(v2 - v1);
                const float r1 = 1.0f / (1.0f + e2);
                const float r2 = 1.0f - r1;

                out[(size_t)tok * 2 + 0] = r1;
                out[(size_t)tok * 2 + 1] = r2;
                out[(size_t)idx_off + (size_t)tok * 2 + 0] = (float)i1;
                out[(size_t)idx_off + (size_t)tok * 2 + 1] = (float)i2;
            }
        }
    }
    #undef ISSUE_STAGE
}

extern "C" void kernel_launch(void* const* d_in, const int* in_sizes, int n_in,
                              void* d_out, int out_size)
{
    const float* x = (const float*)d_in[0];
    const float* W = (const float*)d_in[1];
    const float* b = (const float*)d_in[2];
    float* out = (float*)d_out;

    const int idx_off = out_size / 2;

    cudaFuncSetAttribute(gating_kernel,
                         cudaFuncAttributeMaxDynamicSharedMemorySize,
                         (int)SMEM_BYTES);

    gating_kernel<<<GRID, THREADS, SMEM_BYTES>>>(x, W, b, out, idx_off);
}

// round 4
// speedup vs baseline: 1.1956x; 1.0838x over previous
#include <cuda_runtime.h>
#include <math.h>

#define D_MODEL   3072
#define NUM_E     8
#define N_TOKENS  16384
#define TPW       4                       // tokens per warp-quad
#define WARPS_PB  16
#define THREADS   (WARPS_PB * 32)         // 512
#define CHUNK_D   128                     // floats of D per pipeline stage
#define NCHUNK    (D_MODEL / CHUNK_D)     // 24
#define NSTAGE    3                       // per-warp ring depth
#define GRID      148
#define NWARPS_G  (GRID * WARPS_PB)       // 2368 global warps
#define NQUADS    (N_TOKENS / TPW)        // 4096
#define ROW_V     (D_MODEL / 4)           // 768 16B elems per W row
#define RING_FLOATS_PER_WARP (NSTAGE * TPW * CHUNK_D)    // 1536
#define SMEM_BYTES ((NUM_E * D_MODEL + WARPS_PB * RING_FLOATS_PER_WARP) * 4)  // 192 KB

typedef unsigned long long u64;

__device__ __forceinline__ u64 ffma2(u64 a, u64 b, u64 c) {
    u64 d;
    asm("fma.rn.f32x2 %0, %1, %2, %3;" : "=l"(d) : "l"(a), "l"(b), "l"(c));
    return d;
}
__device__ __forceinline__ float unpack_sum(u64 v) {
    return __uint_as_float((unsigned)(v & 0xFFFFFFFFull)) +
           __uint_as_float((unsigned)(v >> 32));
}

__global__ void __launch_bounds__(THREADS, 1)
gating_kernel(const float* __restrict__ x,
              const float* __restrict__ W,
              const float* __restrict__ b,
              float* __restrict__ out,
              int idx_off)
{
    extern __shared__ float smem[];
    float* sW = smem;                                   // [8][3072]
    float* sX = smem + NUM_E * D_MODEL;                 // per-warp rings

    {
        const float4* Wv = reinterpret_cast<const float4*>(W);
        float4* sWv4 = reinterpret_cast<float4*>(sW);
        #pragma unroll 4
        for (int i = threadIdx.x; i < NUM_E * D_MODEL / 4; i += THREADS)
            sWv4[i] = Wv[i];
    }
    __syncthreads();

    const int warp = threadIdx.x >> 5;
    const int lane = threadIdx.x & 31;
    const int bid  = blockIdx.x;

    float* ring = sX + warp * RING_FLOATS_PER_WARP;
    const unsigned ring_s =
        (unsigned)__cvta_generic_to_shared(ring) + lane * 16;
    const ulonglong2* __restrict__ ringv =
        reinterpret_cast<const ulonglong2*>(ring);
    const ulonglong2* __restrict__ sWv =
        reinterpret_cast<const ulonglong2*>(sW);

    // Round-robin over CTAs first, then warps, so per-SM quad counts are
    // balanced to +-1 (27 or 28 per SM) instead of whole-CTA imbalance.
    const int q0 = bid + GRID * warp;                 // first quad, < 2368
    const int nq = (q0 + NWARPS_G < NQUADS) ? 2 : 1;  // 1 or 2 quads
    const int T  = nq * NCHUNK;

    // stage t -> quad j = t/24, chunk c = t%24, ring slot t%3
    #define ISSUE_STAGE(t_)                                                   \
        do {                                                                  \
            int _t = (t_);                                                    \
            int _j = _t / NCHUNK;                                             \
            int _c = _t - _j * NCHUNK;                                        \
            int _q = q0 + _j * NWARPS_G;                                      \
            const float* _src = x + (size_t)_q * (TPW * D_MODEL)              \
                                  + _c * CHUNK_D + lane * 4;                  \
            unsigned _dst = ring_s + (_t % NSTAGE) * (TPW * CHUNK_D * 4);     \
            _Pragma("unroll")                                                 \
            for (int _tt = 0; _tt < TPW; ++_tt)                               \
                asm volatile("cp.async.cg.shared.global [%0], [%1], 16;"      \
                             :: "r"(_dst + _tt * (CHUNK_D * 4)),              \
                                "l"(_src + (size_t)_tt * D_MODEL));           \
        } while (0)

    u64 acc[TPW][NUM_E];
    #pragma unroll
    for (int t = 0; t < TPW; ++t)
        #pragma unroll
        for (int e = 0; e < NUM_E; ++e)
            acc[t][e] = 0ull;

    // Prologue: 2 stages in flight.
    ISSUE_STAGE(0);
    asm volatile("cp.async.commit_group;" ::: "memory");
    ISSUE_STAGE(1);
    asm volatile("cp.async.commit_group;" ::: "memory");

    for (int t = 0; t < T; ++t) {
        // stage t complete (<=1 younger group still pending)
        asm volatile("cp.async.wait_group 1;" ::: "memory");

        if (t + 2 < T) ISSUE_STAGE(t + 2);
        asm volatile("cp.async.commit_group;" ::: "memory");

        const int j = t / NCHUNK;
        const int c = t - j * NCHUNK;
        const int slot = t % NSTAGE;

        const ulonglong2* xs = ringv + slot * (TPW * CHUNK_D / 4);
        ulonglong2 xv[TPW];
        #pragma unroll
        for (int tt = 0; tt < TPW; ++tt)
            xv[tt] = xs[tt * (CHUNK_D / 4) + lane];

        #pragma unroll
        for (int e = 0; e < NUM_E; ++e) {
            const ulonglong2 wv = sWv[e * ROW_V + c * (CHUNK_D / 4) + lane];
            #pragma unroll
            for (int tt = 0; tt < TPW; ++tt) {
                acc[tt][e] = ffma2(xv[tt].x, wv.x, acc[tt][e]);
                acc[tt][e] = ffma2(xv[tt].y, wv.y, acc[tt][e]);
            }
        }

        if (c == NCHUNK - 1) {
            // ---- epilogue for quad q = q0 + j*NWARPS_G ----
            const int tok0 = (q0 + j * NWARPS_G) * TPW;

            float red[TPW][NUM_E];
            #pragma unroll
            for (int tt = 0; tt < TPW; ++tt)
                #pragma unroll
                for (int e = 0; e < NUM_E; ++e) {
                    red[tt][e] = unpack_sum(acc[tt][e]);
                    acc[tt][e] = 0ull;
                }

            #pragma unroll
            for (int off = 16; off > 0; off >>= 1)
                #pragma unroll
                for (int tt = 0; tt < TPW; ++tt)
                    #pragma unroll
                    for (int e = 0; e < NUM_E; ++e)
                        red[tt][e] += __shfl_xor_sync(0xFFFFFFFFu, red[tt][e], off);

            if (lane < TPW) {
                const int tok = tok0 + lane;

                float logit[NUM_E];
                #pragma unroll
                for (int e = 0; e < NUM_E; ++e)
                    logit[e] = red[lane][e] + __ldg(&b[e]);

                float m = logit[0];
                #pragma unroll
                for (int e = 1; e < NUM_E; ++e) m = fmaxf(m, logit[e]);

                float ex[NUM_E], Z = 0.0f;
                #pragma unroll
                for (int e = 0; e < NUM_E; ++e) { ex[e] = __expf(logit[e] - m); Z += ex[e]; }
                const float invZ = 1.0f / Z;

                float sc[NUM_E];
                #pragma unroll
                for (int e = 0; e < NUM_E; ++e) sc[e] = ex[e] * invZ;

                int i1 = 0;
                #pragma unroll
                for (int e = 1; e < NUM_E; ++e) if (sc[e] > sc[i1]) i1 = e;
                int i2 = (i1 == 0) ? 1 : 0;
                #pragma unroll
                for (int e = 0; e < NUM_E; ++e)
                    if (e != i1 && sc[e] > sc[i2]) i2 = e;

                const float v1 = sc[i1];
                const float v2 = sc[i2];
                const float e2 = __expf(v2 - v1);
                const float r1 = 1.0f / (1.0f + e2);
                const float r2 = 1.0f - r1;

                out[(size_t)tok * 2 + 0] = r1;
                out[(size_t)tok * 2 + 1] = r2;
                out[(size_t)idx_off + (size_t)tok * 2 + 0] = (float)i1;
                out[(size_t)idx_off + (size_t)tok * 2 + 1] = (float)i2;
            }
        }
    }
    #undef ISSUE_STAGE
}

extern "C" void kernel_launch(void* const* d_in, const int* in_sizes, int n_in,
                              void* d_out, int out_size)
{
    const float* x = (const float*)d_in[0];
    const float* W = (const float*)d_in[1];
    const float* b = (const float*)d_in[2];
    float* out = (float*)d_out;

    const int idx_off = out_size / 2;

    cudaFuncSetAttribute(gating_kernel,
                         cudaFuncAttributeMaxDynamicSharedMemorySize,
                         (int)SMEM_BYTES);

    gating_kernel<<<GRID, THREADS, SMEM_BYTES>>>(x, W, b, out, idx_off);
}